// round 17
// baseline (speedup 1.0000x reference)
#include <cuda_runtime.h>
#include <cuda_fp16.h>
#include <cstdint>

#define TSEQ 200
#define PSTEPS 50
#define BATCHN 32768
#define GSAMP 16
#define NCTA (BATCHN / GSAMP)   // 2048
#define XH_STR 40               // f16 elems per row (80B, 16B aligned, conflict-free ldsm)
#define XX_STR 8                // 16B rows (k8 x-chunk)
#define H05 0x38003800u         // (0.5, 0.5) f16x2

// ---------------- helpers ----------------
__device__ __forceinline__ uint32_t s2u(const void* p) {
    uint32_t a;
    asm("{ .reg .u64 t; cvta.to.shared.u64 t, %1; cvt.u32.u64 %0, t; }" : "=r"(a) : "l"(p));
    return a;
}
__device__ __forceinline__ uint32_t packh(float a, float b) {  // (f16(a), f16(b))
    uint32_t r;
    asm("{.reg .b16 x,y; cvt.rn.f16.f32 x, %1; cvt.rn.f16.f32 y, %2; mov.b32 %0, {x,y};}"
        : "=r"(r) : "f"(a), "f"(b));
    return r;
}
__device__ __forceinline__ uint32_t tanh2(uint32_t x) {
    uint32_t r; asm("tanh.approx.f16x2 %0, %1;" : "=r"(r) : "r"(x)); return r;
}
__device__ __forceinline__ uint32_t mul2(uint32_t a, uint32_t b) {
    uint32_t r; asm("mul.rn.f16x2 %0, %1, %2;" : "=r"(r) : "r"(a), "r"(b)); return r;
}
__device__ __forceinline__ uint32_t fma2h(uint32_t a, uint32_t b, uint32_t c) {
    uint32_t r; asm("fma.rn.f16x2 %0, %1, %2, %3;" : "=r"(r) : "r"(a), "r"(b), "r"(c)); return r;
}
// gates arrive pre-scaled by 0.5 (folded into weights): sigm = 0.5*tanh(g') + 0.5
__device__ __forceinline__ uint32_t sigm2f(uint32_t gpre) {
    return fma2h(H05, tanh2(gpre), H05);
}
// f16-accumulator gate MMAs
__device__ __forceinline__ void mma16816h(uint32_t* d, const uint32_t* a, const uint32_t* b) {
    asm volatile("mma.sync.aligned.m16n8k16.row.col.f16.f16.f16.f16 "
                 "{%0,%1}, {%2,%3,%4,%5}, {%6,%7}, {%0,%1};"
                 : "+r"(d[0]), "+r"(d[1])
                 : "r"(a[0]), "r"(a[1]), "r"(a[2]), "r"(a[3]), "r"(b[0]), "r"(b[1]));
}
__device__ __forceinline__ void mma1688h(uint32_t* d, const uint32_t* a, uint32_t b) {
    asm volatile("mma.sync.aligned.m16n8k8.row.col.f16.f16.f16.f16 "
                 "{%0,%1}, {%2,%3}, {%4}, {%0,%1};"
                 : "+r"(d[0]), "+r"(d[1])
                 : "r"(a[0]), "r"(a[1]), "r"(b));
}
// f32-accumulator MMA (pred output path only — error there is undamped)
__device__ __forceinline__ void mma16816(float* d, const uint32_t* a, const uint32_t* b) {
    asm volatile("mma.sync.aligned.m16n8k16.row.col.f32.f16.f16.f32 "
                 "{%0,%1,%2,%3}, {%4,%5,%6,%7}, {%8,%9}, {%0,%1,%2,%3};"
                 : "+f"(d[0]), "+f"(d[1]), "+f"(d[2]), "+f"(d[3])
                 : "r"(a[0]), "r"(a[1]), "r"(a[2]), "r"(a[3]), "r"(b[0]), "r"(b[1]));
}
__device__ __forceinline__ void ldsm4(uint32_t* r, uint32_t addr) {
    asm volatile("ldmatrix.sync.aligned.m8n8.x4.shared.b16 {%0,%1,%2,%3}, [%4];"
                 : "=r"(r[0]), "=r"(r[1]), "=r"(r[2]), "=r"(r[3]) : "r"(addr));
}
__device__ __forceinline__ void ldsm2(uint32_t* r, uint32_t addr) {
    asm volatile("ldmatrix.sync.aligned.m8n8.x2.shared.b16 {%0,%1}, [%2];"
                 : "=r"(r[0]), "=r"(r[1]) : "r"(addr));
}
__device__ __forceinline__ void sts32(uint32_t v, uint32_t a) {
    asm volatile("st.shared.b32 [%0], %1;" :: "r"(a), "r"(v));
}

// Gate-major map, 2 warps x N=64: tile t (0..7) -> gate gt = t&3 (i,f,g,o),
// unit block = 16w + 8*(t>>2), col c = unit offset.  Lane j's dg[t][rr] is
// the f16x2 (gate gt of units [16w+8s+2j, +1]) at row r+8rr, s = t>>2.
// Weight row: pr = gt*32 + 16w + 8*(t>>2) + c.  Fold 0.5 into i,f,o gates.

__global__ void __launch_bounds__(64, 12) lstm_hmma_kernel(
    const float* __restrict__ hist,
    const float* __restrict__ Wih,
    const float* __restrict__ Whh,
    const float* __restrict__ bih,
    const float* __restrict__ bhh,
    const float* __restrict__ Wpred,
    const float* __restrict__ bpred,
    float* __restrict__ out)
{
    __shared__ __align__(16) __half Xhi[2][GSAMP][XH_STR];
    __shared__ __align__(16) __half Xx [2][GSAMP][XX_STR];

    const int tid  = threadIdx.x;
    const int lane = tid & 31;
    const int w    = tid >> 5;          // 0 or 1
    const int S0   = blockIdx.x * GSAMP;

    const int j    = lane & 3;
    const int nsub = lane >> 2;
    const int k0   = 2 * j;

    uint32_t Bh[8][2][2], Bx[8];        // Whh f16 (0.5-folded); x-chunk k8
    uint32_t Ph[2][2];                  // warp1 pred tile (decode)

#pragma unroll
    for (int t = 0; t < 8; t++) {
        int gt = t & 3;
        int pr = gt * 32 + 16 * w + 8 * (t >> 2) + nsub;
        float sc = (gt == 2) ? 1.0f : 0.5f;
#pragma unroll
        for (int c = 0; c < 2; c++) {
            int kb = c * 16;
            Bh[t][c][0] = packh(sc * Whh[pr * 32 + kb + k0],
                                sc * Whh[pr * 32 + kb + k0 + 1]);
            Bh[t][c][1] = packh(sc * Whh[pr * 32 + kb + k0 + 8],
                                sc * Whh[pr * 32 + kb + k0 + 9]);
        }
        // x-chunk (k8): rows 0-3 = Wih cols, row 4 = bias (A row 4 = ones)
        float v0 = 0.0f, v1 = 0.0f;
        if (j == 0)      { v0 = sc * Wih[pr * 4 + 0]; v1 = sc * Wih[pr * 4 + 1]; }
        else if (j == 1) { v0 = sc * Wih[pr * 4 + 2]; v1 = sc * Wih[pr * 4 + 3]; }
        else if (j == 2) { v0 = sc * (bih[pr] + bhh[pr]); }
        Bx[t] = packh(v0, v1);
    }

    // ---------------- prime smem ----------------
    for (int i = tid; i < GSAMP * XH_STR; i += 64) {
        Xhi[0][i / XH_STR][i % XH_STR] = __float2half(0.0f);
    }
    if (tid < GSAMP) {
        const float4 x = ((const float4*)hist)[(size_t)(S0 + tid) * TSEQ];
        uint4 q;
        q.x = packh(x.x, x.y); q.y = packh(x.z, x.w);
        q.z = packh(1.0f, 0.0f); q.w = 0u;
        ((uint4*)&Xx[0][tid][0])[0] = q;
    }
    __syncthreads();

    // ldmatrix addressing
    const int mrow  = (lane & 7) + ((lane >> 3) & 1) * 8;
    const int mkoff = ((lane >> 4) & 1) * 16;      // bytes (Xhi x4 only)
    const uint32_t aXhi = s2u(&Xhi[0][0][0]);
    const uint32_t aXx  = s2u(&Xx[0][0][0]);
    const uint32_t PAR_H = GSAMP * XH_STR * 2;     // parity stride bytes
    const uint32_t PAR_X = GSAMP * XX_STR * 2;     // 256B

    const int r = lane >> 2;                       // sample row (and r+8)
    // unit pair for tile group s: u0(s) = 16w + 8s + 2j

    uint32_t cst2[2][2] = {{0u, 0u}, {0u, 0u}};    // c f16x2 per (s, rr)
    int p = 0;

    // =================== encoder: 200 steps ===================
    for (int step = 0; step < TSEQ; step++) {
        uint32_t Ah0[4], Ah1[4], Ax[2];
        {
            uint32_t ah = aXhi + (uint32_t)p * PAR_H + (uint32_t)mrow * (XH_STR * 2) + mkoff;
            uint32_t ax = aXx  + (uint32_t)p * PAR_X + (uint32_t)(lane & 15) * (XX_STR * 2);
            ldsm4(Ah0, ah); ldsm4(Ah1, ah + 32);
            ldsm2(Ax, ax);
        }

        // prefetch next encoder x while MMAs run
        float4 xn;
        const bool wantx = (step + 1 < TSEQ) && (w == 0) && (lane < GSAMP);
        if (wantx) xn = ((const float4*)hist)[(size_t)(S0 + lane) * TSEQ + step + 1];

        uint32_t dg[8][2];
#pragma unroll
        for (int t = 0; t < 8; t++) {
            dg[t][0] = 0u; dg[t][1] = 0u;
            mma16816h(dg[t], Ah0, Bh[t][0]);
            mma16816h(dg[t], Ah1, Bh[t][1]);
            mma1688h(dg[t], Ax, Bx[t]);
        }

        // ---- epilogue: 4 independent blocks (s x rr), no repack ----
        const uint32_t hbase = aXhi + (uint32_t)(p ^ 1) * PAR_H;
#pragma unroll
        for (int s = 0; s < 2; s++) {
            int u0 = 16 * w + 8 * s + 2 * j;
#pragma unroll
            for (int rr = 0; rr < 2; rr++) {
                uint32_t itg = mul2(sigm2f(dg[4 * s + 0][rr]), tanh2(dg[4 * s + 2][rr]));
                uint32_t cn2 = fma2h(sigm2f(dg[4 * s + 1][rr]), cst2[s][rr], itg);
                cst2[s][rr] = cn2;
                uint32_t h2 = mul2(sigm2f(dg[4 * s + 3][rr]), tanh2(cn2));
                int row = r + rr * 8;
                sts32(h2, hbase + (uint32_t)(row * XH_STR + u0) * 2u);
            }
        }

        if (wantx) {
            uint4 q;
            q.x = packh(xn.x, xn.y); q.y = packh(xn.z, xn.w);
            q.z = packh(1.0f, 0.0f); q.w = 0u;
            ((uint4*)&Xx[p ^ 1][lane][0])[0] = q;
        }

        __syncthreads();
        p ^= 1;
    }

    // =================== decode boundary: fused weights ===================
#pragma unroll
    for (int t = 0; t < 8; t++) {
        int gt = t & 3;
        int pr = gt * 32 + 16 * w + 8 * (t >> 2) + nsub;
        float sc = (gt == 2) ? 1.0f : 0.5f;
#pragma unroll
        for (int c = 0; c < 2; c++) {
            int kb = c * 16;
            float wv[4];
#pragma unroll
            for (int q = 0; q < 4; q++) {
                int kk = kb + ((q < 2) ? k0 : k0 + 8) + (q & 1);
                float v = Whh[pr * 32 + kk];
#pragma unroll
                for (int d = 0; d < 4; d++)
                    v += Wih[pr * 4 + d] * Wpred[d * 32 + kk];
                wv[q] = sc * v;
            }
            Bh[t][c][0] = packh(wv[0], wv[1]);
            Bh[t][c][1] = packh(wv[2], wv[3]);
        }
        // Bx becomes the per-lane d-frag bias initializer: unit pair of tile t
        {
            int pr0 = gt * 32 + 16 * w + 8 * (t >> 2) + 2 * j;
            int pr1 = pr0 + 1;
            float b0 = bih[pr0] + bhh[pr0];
            float b1 = bih[pr1] + bhh[pr1];
#pragma unroll
            for (int d = 0; d < 4; d++) {
                b0 += Wih[pr0 * 4 + d] * bpred[d];
                b1 += Wih[pr1 * 4 + d] * bpred[d];
            }
            Bx[t] = packh(sc * b0, sc * b1);
        }
    }
    // pred tile (warp1): cols = pred dims 0-3 (4-7 zero); bias via dp init
    {
        int d = nsub;
        bool ok = (d < 4);
#pragma unroll
        for (int c = 0; c < 2; c++) {
            int kb = c * 16;
            Ph[c][0] = packh(ok ? Wpred[d * 32 + kb + k0]     : 0.0f,
                             ok ? Wpred[d * 32 + kb + k0 + 1] : 0.0f);
            Ph[c][1] = packh(ok ? Wpred[d * 32 + kb + k0 + 8] : 0.0f,
                             ok ? Wpred[d * 32 + kb + k0 + 9] : 0.0f);
        }
    }
    const float bp0 = (j < 2) ? bpred[2 * j]     : 0.0f;
    const float bp1 = (j < 2) ? bpred[2 * j + 1] : 0.0f;

    // =================== decode: 50 steps (f gate dead: c resets) ===========
    for (int ps = 0; ps < PSTEPS; ps++) {
        uint32_t Ah0[4], Ah1[4];
        {
            uint32_t ah = aXhi + (uint32_t)p * PAR_H + (uint32_t)mrow * (XH_STR * 2) + mkoff;
            ldsm4(Ah0, ah); ldsm4(Ah1, ah + 32);
        }

        // gates i (t=4s), g (t=4s+2), o (t=4s+3); bias-initialized accums
        uint32_t dgi[2][2], dgg[2][2], dgo[2][2];
#pragma unroll
        for (int s = 0; s < 2; s++) {
            dgi[s][0] = Bx[4 * s + 0]; dgi[s][1] = Bx[4 * s + 0];
            dgg[s][0] = Bx[4 * s + 2]; dgg[s][1] = Bx[4 * s + 2];
            dgo[s][0] = Bx[4 * s + 3]; dgo[s][1] = Bx[4 * s + 3];
            mma16816h(dgi[s], Ah0, Bh[4 * s + 0][0]); mma16816h(dgi[s], Ah1, Bh[4 * s + 0][1]);
            mma16816h(dgg[s], Ah0, Bh[4 * s + 2][0]); mma16816h(dgg[s], Ah1, Bh[4 * s + 2][1]);
            mma16816h(dgo[s], Ah0, Bh[4 * s + 3][0]); mma16816h(dgo[s], Ah1, Bh[4 * s + 3][1]);
        }

        if (w == 1) {   // pred in f32 accum, bias-initialized
            float dp[4] = {bp0, bp1, bp0, bp1};
            mma16816(dp, Ah0, Ph[0]);
            mma16816(dp, Ah1, Ph[1]);
            if (j < 2) {
                float2* o0 = (float2*)(out + (size_t)(S0 + r)     * (PSTEPS * 4) + ps * 4 + k0);
                float2* o1 = (float2*)(out + (size_t)(S0 + r + 8) * (PSTEPS * 4) + ps * 4 + k0);
                *o0 = make_float2(dp[0], dp[1]);
                *o1 = make_float2(dp[2], dp[3]);
            }
        }

        const uint32_t hbase = aXhi + (uint32_t)(p ^ 1) * PAR_H;
#pragma unroll
        for (int s = 0; s < 2; s++) {
            int u0 = 16 * w + 8 * s + 2 * j;
#pragma unroll
            for (int rr = 0; rr < 2; rr++) {
                uint32_t cn2 = mul2(sigm2f(dgi[s][rr]), tanh2(dgg[s][rr]));   // c resets
                uint32_t h2  = mul2(sigm2f(dgo[s][rr]), tanh2(cn2));
                int row = r + rr * 8;
                sts32(h2, hbase + (uint32_t)(row * XH_STR + u0) * 2u);
            }
        }

        __syncthreads();
        p ^= 1;
    }
}

extern "C" void kernel_launch(void* const* d_in, const int* in_sizes, int n_in,
                              void* d_out, int out_size) {
    const float* hist  = (const float*)d_in[0];
    const float* Wih   = (const float*)d_in[1];
    const float* Whh   = (const float*)d_in[2];
    const float* bih   = (const float*)d_in[3];
    const float* bhh   = (const float*)d_in[4];
    const float* Wpred = (const float*)d_in[5];
    const float* bpred = (const float*)d_in[6];
    lstm_hmma_kernel<<<NCTA, 64>>>(hist, Wih, Whh, bih, bhh, Wpred, bpred,
                                   (float*)d_out);
}